// round 8
// baseline (speedup 1.0000x reference)
#include <cuda_runtime.h>

#define NBLK 128

// ---------------- scratch (__device__ globals; no allocation allowed) ----------------
__device__ float g_hx[8*32*256];
__device__ float g_hy[8*32*256];
__device__ float g_hz[8*32*256];
__device__ float g_attraw[8*2*32768];        // pre-softmax logits [b][h][x][y][z]
__device__ float g_partmax[8*2*32];          // per (b,h,x) block max
__device__ float g_partsum[8*2*32];          // per (b,h,x) Σexp(v - localmax)
__device__ float g_part[8*32*256];           // per (b,x) logits partials
__device__ unsigned g_count = 0;             // grid-barrier arrive counter
__device__ unsigned g_gen   = 0;             // grid-barrier generation

// ---------------- software grid barrier (all NBLK blocks co-resident) ----------------
__device__ __forceinline__ void gsync() {
    __syncthreads();
    if (threadIdx.x == 0) {
        __threadfence();                                   // publish my writes
        unsigned gen = *(volatile unsigned*)&g_gen;
        if (atomicAdd(&g_count, 1u) == NBLK - 1) {
            g_count = 0;
            __threadfence();
            atomicAdd(&g_gen, 1u);                         // release
        } else {
            while (*(volatile unsigned*)&g_gen == gen) { }
        }
        __threadfence();                                   // acquire
    }
    __syncthreads();
}

// ---------------- shared memory union across phases ----------------
union SMem {
    struct { float sIn[32*128]; float sV[64*33]; float red[256]; } proj;   // ~26 KB
    struct { float st[32*64];  float sw[64*68]; float red[256]; } att;     // ~27 KB
    struct { float sa[1024];   float shz[256*36]; float sstat[4]; } fuse;  // ~41 KB
};

// ---------------- the single persistent kernel ----------------
__global__ void __launch_bounds__(256) k_all(
    const float* __restrict__ xin, const float* __restrict__ yin, const float* __restrict__ zin,
    const float* __restrict__ Vx, const float* __restrict__ gx, const float* __restrict__ bx,
    const float* __restrict__ Vy, const float* __restrict__ gy, const float* __restrict__ by,
    const float* __restrict__ Vz, const float* __restrict__ gz, const float* __restrict__ bz,
    const float* __restrict__ Vh, const float* __restrict__ ghp, const float* __restrict__ bhp,
    const float* __restrict__ gamma, const float* __restrict__ beta,
    float* __restrict__ outp, float* __restrict__ att_out) {

    __shared__ SMem sm;
    int tid = threadIdx.x;
    int blk = blockIdx.x;

    // ============ PHASE 1: projections  h = relu(in @ (g/||V||*V)^T + b) ============
    // 96 tasks: (q 4) x (b 8) x (m 3)
    if (blk < 96) {
        int q = blk & 3, b = (blk >> 2) & 7, m = blk >> 5;
        const float* in   = (m == 0) ? xin : (m == 1) ? yin : zin;
        const float* V    = (m == 0) ? Vx  : (m == 1) ? Vy  : Vz;
        const float* gp   = (m == 0) ? gx  : (m == 1) ? gy  : gz;
        const float* bias = (m == 0) ? bx  : (m == 1) ? by  : bz;
        float* out        = (m == 0) ? g_hx : (m == 1) ? g_hy : g_hz;
        int k0 = q * 64;

        for (int e = tid; e < 4096; e += 256) sm.proj.sIn[e] = in[b * 4096 + e];
        float ss = 0.f;
        for (int i = tid; i < 32768; i += 256) { float v = V[i]; ss += v * v; }
        sm.proj.red[tid] = ss; __syncthreads();
        for (int s = 128; s > 0; s >>= 1) {
            if (tid < s) sm.proj.red[tid] += sm.proj.red[tid + s];
            __syncthreads();
        }
        float scale = gp[0] / sqrtf(sm.proj.red[0]);

        int kk = tid & 63, rg = tid >> 6, r0 = rg * 8;
        float acc[8] = {0,0,0,0,0,0,0,0};
        for (int dc = 0; dc < 128; dc += 32) {
            __syncthreads();
            for (int e = tid; e < 2048; e += 256) {
                int kr = e >> 5, d = e & 31;
                sm.proj.sV[kr * 33 + d] = V[(k0 + kr) * 128 + dc + d];
            }
            __syncthreads();
            for (int d = 0; d < 32; d += 4) {
                float v0 = sm.proj.sV[kk*33 + d],     v1 = sm.proj.sV[kk*33 + d + 1];
                float v2 = sm.proj.sV[kk*33 + d + 2], v3 = sm.proj.sV[kk*33 + d + 3];
                #pragma unroll
                for (int r = 0; r < 8; r++) {
                    float4 iv = *(const float4*)&sm.proj.sIn[(r0 + r) * 128 + dc + d];
                    acc[r] += iv.x * v0 + iv.y * v1 + iv.z * v2 + iv.w * v3;
                }
            }
        }
        float bb = bias[k0 + kk];
        #pragma unroll
        for (int r = 0; r < 8; r++) {
            float v = acc[r] * scale + bb;
            out[(b * 32 + r0 + r) * 256 + k0 + kk] = v > 0.f ? v : 0.f;
        }
    }
    gsync();

    // ============ PHASE 2: att GEMM + online-softmax partials ============
    // 256 tasks (32 x, 8 b), 2 per block. Thread tile: 2y x 4zh.
    {
        // ||Vh|| once per block
        float ssh = 0.f;
        for (int i = tid; i < 512; i += 256) { float v = Vh[i]; ssh += v * v; }
        sm.att.red[tid] = ssh; __syncthreads();
        for (int s = 128; s > 0; s >>= 1) { if (tid < s) sm.att.red[tid] += sm.att.red[tid + s]; __syncthreads(); }
        float scaleH = ghp[0] / sqrtf(sm.att.red[0]);
        float b0 = bhp[0], b1 = bhp[1];

        for (int task = blk; task < 256; task += NBLK) {
            int x = task & 31, b = task >> 5;
            int yg = tid >> 4, zg = tid & 15;           // y pair = yg*2+{0,1}; zh quad = zg*4..+3
            float4 acc[2];
            acc[0] = acc[1] = make_float4(0.f, 0.f, 0.f, 0.f);
            const float* hx  = g_hx + (b * 32 + x) * 256;
            const float* hyB = g_hy + b * 8192;
            const float* hzB = g_hz + b * 8192;
            for (int c = 0; c < 4; c++) {
                int k0 = c * 64;
                __syncthreads();
                for (int e = tid; e < 2048; e += 256) {
                    int kc = e & 63, y = e >> 6;
                    sm.att.st[y * 64 + kc] = hx[k0 + kc] * hyB[y * 256 + k0 + kc];
                }
                for (int e = tid; e < 4096; e += 256) {
                    int kc = e & 63, zh = e >> 6;
                    sm.att.sw[kc * 68 + zh] = hzB[(zh >> 1) * 256 + k0 + kc] *
                                              Vh[(zh & 1) * 256 + k0 + kc] * scaleH;
                }
                __syncthreads();
                #pragma unroll 4
                for (int kc = 0; kc < 64; kc++) {
                    float4 w = *(const float4*)&sm.att.sw[kc * 68 + zg * 4];
                    float t0 = sm.att.st[(yg*2 + 0) * 64 + kc];
                    float t1 = sm.att.st[(yg*2 + 1) * 64 + kc];
                    acc[0].x += t0*w.x; acc[0].y += t0*w.y; acc[0].z += t0*w.z; acc[0].w += t0*w.w;
                    acc[1].x += t1*w.x; acc[1].y += t1*w.y; acc[1].z += t1*w.z; acc[1].w += t1*w.w;
                }
            }
            float m0 = -1e30f, m1 = -1e30f;
            float* r0base = g_attraw + ((b * 2 + 0) * 32 + x) * 1024;
            float* r1base = g_attraw + ((b * 2 + 1) * 32 + x) * 1024;
            int z0 = zg * 2;
            #pragma unroll
            for (int i = 0; i < 2; i++) {
                int y = yg * 2 + i;
                float4 v = acc[i];
                v.x += b0; v.y += b1; v.z += b0; v.w += b1;
                m0 = fmaxf(m0, fmaxf(v.x, v.z));
                m1 = fmaxf(m1, fmaxf(v.y, v.w));
                r0base[y * 32 + z0]     = v.x;   // (h=0, z=z0)
                r1base[y * 32 + z0]     = v.y;   // (h=1, z=z0)
                r0base[y * 32 + z0 + 1] = v.z;   // (h=0, z=z0+1)
                r1base[y * 32 + z0 + 1] = v.w;   // (h=1, z=z0+1)
            }
            __syncthreads();
            sm.att.red[tid] = m0; __syncthreads();
            for (int s = 128; s > 0; s >>= 1) { if (tid < s) sm.att.red[tid] = fmaxf(sm.att.red[tid], sm.att.red[tid + s]); __syncthreads(); }
            float M0 = sm.att.red[0]; __syncthreads();
            sm.att.red[tid] = m1; __syncthreads();
            for (int s = 128; s > 0; s >>= 1) { if (tid < s) sm.att.red[tid] = fmaxf(sm.att.red[tid], sm.att.red[tid + s]); __syncthreads(); }
            float M1 = sm.att.red[0]; __syncthreads();
            float s0 = 0.f, s1 = 0.f;
            #pragma unroll
            for (int i = 0; i < 2; i++) {
                float4 v = acc[i];
                s0 += expf(v.x + b0 - M0) + expf(v.z + b0 - M0);
                s1 += expf(v.y + b1 - M1) + expf(v.w + b1 - M1);
            }
            sm.att.red[tid] = s0; __syncthreads();
            for (int s = 128; s > 0; s >>= 1) { if (tid < s) sm.att.red[tid] += sm.att.red[tid + s]; __syncthreads(); }
            float S0 = sm.att.red[0]; __syncthreads();
            sm.att.red[tid] = s1; __syncthreads();
            for (int s = 128; s > 0; s >>= 1) { if (tid < s) sm.att.red[tid] += sm.att.red[tid + s]; __syncthreads(); }
            if (tid == 0) {
                g_partmax[(b * 2 + 0) * 32 + x] = M0;
                g_partmax[(b * 2 + 1) * 32 + x] = M1;
                g_partsum[(b * 2 + 0) * 32 + x] = S0;
                g_partsum[(b * 2 + 1) * 32 + x] = sm.att.red[0];
            }
            __syncthreads();
        }
    }
    gsync();

    // ============ PHASE 3: softmax-finalize + att_out + logits partials ============
    // 256 tasks (32 x, 8 b), 2 per block.
    for (int task = blk; task < 256; task += NBLK) {
        int x = task & 31, b = task >> 5;
        __syncthreads();
        for (int e = tid; e < 8192; e += 256) {
            int k = e & 255, z = e >> 8;
            sm.fuse.shz[k * 36 + z] = g_hz[(b * 32 + z) * 256 + k];
        }
        if (tid < 64) {
            int h = tid >> 5, lane = tid & 31;
            float m = g_partmax[(b * 2 + h) * 32 + lane];
            float s = g_partsum[(b * 2 + h) * 32 + lane];
            float M = m;
            #pragma unroll
            for (int o = 16; o > 0; o >>= 1) M = fmaxf(M, __shfl_xor_sync(0xffffffffu, M, o));
            float se = s * expf(m - M);
            #pragma unroll
            for (int o = 16; o > 0; o >>= 1) se += __shfl_xor_sync(0xffffffffu, se, o);
            if (lane == 0) { sm.fuse.sstat[h * 2] = M; sm.fuse.sstat[h * 2 + 1] = 1.f / se; }
        }
        __syncthreads();
        float M0 = sm.fuse.sstat[0], I0 = sm.fuse.sstat[1];
        float M1 = sm.fuse.sstat[2], I1 = sm.fuse.sstat[3];

        const float* r0 = g_attraw + ((b * 2 + 0) * 32 + x) * 1024;
        const float* r1 = g_attraw + ((b * 2 + 1) * 32 + x) * 1024;
        float* o0 = att_out + ((b * 2 + 0) * 32 + x) * 1024;
        float* o1 = att_out + ((b * 2 + 1) * 32 + x) * 1024;
        #pragma unroll
        for (int i = tid; i < 1024; i += 256) {
            float a0 = expf(r0[i] - M0) * I0;
            float a1 = expf(r1[i] - M1) * I1;
            o0[i] = a0;
            o1[i] = a1;
            sm.fuse.sa[i] = a0 + a1;
        }
        __syncthreads();

        float sxk = g_hx[(b * 32 + x) * 256 + tid];
        const float* hyB = g_hy + b * 8192;
        float acc = 0.f;
        for (int y = 0; y < 32; y++) {
            float s = 0.f;
            #pragma unroll
            for (int z = 0; z < 32; z += 4) {
                float4 a4 = *(const float4*)&sm.fuse.sa[y * 32 + z];
                float4 h4 = *(const float4*)&sm.fuse.shz[tid * 36 + z];
                s += a4.x*h4.x + a4.y*h4.y + a4.z*h4.z + a4.w*h4.w;
            }
            acc += sxk * hyB[y * 256 + tid] * s;
        }
        g_part[(b * 32 + x) * 256 + tid] = acc;
    }
    gsync();

    // ============ PHASE 4: reduce partials over x + BatchNorm ============
    // 32 tasks; warp w of block g owns k = g*8+w.
    if (blk < 32) {
        int warp = tid >> 5, lane = tid & 31;
        int k = blk * 8 + warp;
        float l[8];
        #pragma unroll
        for (int b = 0; b < 8; b++) l[b] = g_part[(b * 32 + lane) * 256 + k];
        #pragma unroll
        for (int b = 0; b < 8; b++) {
            float v = l[b];
            #pragma unroll
            for (int o = 16; o > 0; o >>= 1) v += __shfl_xor_sync(0xffffffffu, v, o);
            l[b] = v;
        }
        float mean = 0.f;
        #pragma unroll
        for (int b = 0; b < 8; b++) mean += l[b];
        mean *= 0.125f;
        float var = 0.f;
        #pragma unroll
        for (int b = 0; b < 8; b++) { float d = l[b] - mean; var += d * d; }
        var *= 0.125f;
        float sc = gamma[k] / sqrtf(var + 1e-5f);
        float bt = beta[k];
        if (lane < 8) outp[lane * 256 + k] = (l[lane] - mean) * sc + bt;
    }
}

// ---------------- launch ----------------
extern "C" void kernel_launch(void* const* d_in, const int* in_sizes, int n_in,
                              void* d_out, int out_size) {
    const float* x     = (const float*)d_in[0];
    const float* y     = (const float*)d_in[1];
    const float* z     = (const float*)d_in[2];
    const float* Vx    = (const float*)d_in[3];
    const float* gx    = (const float*)d_in[4];
    const float* bx    = (const float*)d_in[5];
    const float* Vy    = (const float*)d_in[6];
    const float* gy    = (const float*)d_in[7];
    const float* by    = (const float*)d_in[8];
    const float* Vz    = (const float*)d_in[9];
    const float* gz    = (const float*)d_in[10];
    const float* bz    = (const float*)d_in[11];
    const float* Vh    = (const float*)d_in[12];
    const float* gh    = (const float*)d_in[13];
    const float* bh    = (const float*)d_in[14];
    const float* gamma = (const float*)d_in[15];
    const float* beta  = (const float*)d_in[16];

    float* out     = (float*)d_out;          // [8,256]
    float* att_out = out + 2048;             // [8,2,32,32,32]

    k_all<<<NBLK, 256>>>(x, y, z, Vx, gx, bx, Vy, gy, by, Vz, gz, bz,
                         Vh, gh, bh, gamma, beta, out, att_out);
}